// round 13
// baseline (speedup 1.0000x reference)
#include <cuda_runtime.h>
#include <cuda_fp16.h>
#include <cstdint>
#include <math.h>

#define BB 8
#define DD 512
#define LL 2048
#define HH 8

// fp16 scratch, all pre-swizzled (SW128 chunk perm by row&7 within 64-elem segs)
__device__ __half g_qhi[(size_t)BB * LL * DD];            // [b][l][512] (attn Q)
__device__ __half g_khi[(size_t)BB * LL * DD];            // [b][l][512] (attn K)
__device__ __half g_vhi[(size_t)BB * DD * LL];            // [b][dh][l]  (attn V)
__device__ __half g_whi[(size_t)1536 * DD];               // [o][512]    (proj A, hi)
__device__ __half g_xhi[(size_t)BB * DD * LL];            // [b][d][l]   (proj B hi)
__device__ __half g_xlo[(size_t)BB * DD * LL];            // [b][d][l]   (proj B lo)
__device__ float  g_mkf[(size_t)BB * LL];                 // mask as float {0,1}

// ============================ helpers ======================================
__device__ __forceinline__ uint32_t smem_u32(const void* p) {
    uint32_t a;
    asm("{ .reg .u64 t; cvta.to.shared.u64 t, %1; cvt.u32.u64 %0, t; }"
        : "=r"(a) : "l"(p));
    return a;
}

#define SWZ128(off) ((off) ^ (((off) >> 3) & 0x70))

__device__ __forceinline__ void ldsm4(uint32_t* r, uint32_t addr) {
    asm volatile("ldmatrix.sync.aligned.m8n8.x4.shared.b16 {%0,%1,%2,%3}, [%4];"
        : "=r"(r[0]), "=r"(r[1]), "=r"(r[2]), "=r"(r[3]) : "r"(addr));
}

__device__ __forceinline__ void ldsm4t(uint32_t* r, uint32_t addr) {
    asm volatile("ldmatrix.sync.aligned.m8n8.x4.trans.shared.b16 {%0,%1,%2,%3}, [%4];"
        : "=r"(r[0]), "=r"(r[1]), "=r"(r[2]), "=r"(r[3]) : "r"(addr));
}

__device__ __forceinline__ void mma16816(float* d, const uint32_t* a, const uint32_t* b) {
    asm volatile("mma.sync.aligned.m16n8k16.row.col.f32.f16.f16.f32 "
        "{%0,%1,%2,%3}, {%4,%5,%6,%7}, {%8,%9}, {%0,%1,%2,%3};"
        : "+f"(d[0]), "+f"(d[1]), "+f"(d[2]), "+f"(d[3])
        : "r"(a[0]), "r"(a[1]), "r"(a[2]), "r"(a[3]), "r"(b[0]), "r"(b[1]));
}

__device__ __forceinline__ void cpa16(uint32_t sdst, const void* gsrc) {
    asm volatile("cp.async.cg.shared.global [%0], [%1], 16;"
        :: "r"(sdst), "l"(gsrc));
}
#define CPA_COMMIT() asm volatile("cp.async.commit_group;" ::: "memory")
#define CPA_WAIT(n)  asm volatile("cp.async.wait_group %0;" :: "n"(n) : "memory")

// pack two fp32 into one half2 reg: {lo=a, hi=b}
__device__ __forceinline__ uint32_t pack_h2(float a, float b) {
    uint32_t r;
    asm("cvt.rn.f16x2.f32 %0, %1, %2;" : "=r"(r) : "f"(b), "f"(a));
    return r;
}

// ===========================================================================
// One-shot conversion kernels (fp32/int -> pre-swizzled fp16/float gmem)
// ===========================================================================
__global__ void cvt_w(const float* __restrict__ w_mem, const float* __restrict__ w_q) {
    int idx = blockIdx.x * 256 + threadIdx.x;     // 1536*64
    int o = idx >> 6, ch = idx & 63;
    int seg = ch >> 3, c8 = ch & 7;
    const float* src = (o < 1024 ? w_mem + (size_t)o * DD
                                 : w_q + (size_t)(o - 1024) * DD) + seg * 64 + c8 * 8;
    float4 v0 = *(const float4*)src, v1 = *(const float4*)(src + 4);
    __align__(16) __half h8[8];
    h8[0] = __float2half_rn(v0.x); h8[1] = __float2half_rn(v0.y);
    h8[2] = __float2half_rn(v0.z); h8[3] = __float2half_rn(v0.w);
    h8[4] = __float2half_rn(v1.x); h8[5] = __float2half_rn(v1.y);
    h8[6] = __float2half_rn(v1.z); h8[7] = __float2half_rn(v1.w);
    int pc = c8 ^ (o & 7);
    *(uint4*)&g_whi[(size_t)o * DD + seg * 64 + pc * 8] = *(uint4*)h8;
}

__global__ void cvt_q(const float* __restrict__ qin) {
    int idx = blockIdx.x * 256 + threadIdx.x;     // 8*512*256
    int b = idx >> 17;
    int r = idx & 131071;
    int d = r >> 8, ch = r & 255;
    int seg = ch >> 3, c8 = ch & 7;
    size_t base = ((size_t)b * DD + d) * LL;
    const float* src = qin + base + seg * 64 + c8 * 8;
    float4 v0 = *(const float4*)src, v1 = *(const float4*)(src + 4);
    __align__(16) __half hi8[8], lo8[8];
    float vv[8] = {v0.x, v0.y, v0.z, v0.w, v1.x, v1.y, v1.z, v1.w};
    #pragma unroll
    for (int k = 0; k < 8; k++) {
        __half hx = __float2half_rn(vv[k]);
        hi8[k] = hx;
        lo8[k] = __float2half_rn(vv[k] - __half2float(hx));
    }
    int pc = c8 ^ (d & 7);
    size_t ge = base + seg * 64 + pc * 8;
    *(uint4*)&g_xhi[ge] = *(uint4*)hi8;
    *(uint4*)&g_xlo[ge] = *(uint4*)lo8;
}

__global__ void cvt_m(const int* __restrict__ mask) {
    int i = blockIdx.x * 256 + threadIdx.x;       // 16384
    g_mkf[i] = (float)mask[i];
}

// ===========================================================================
// Projection GEMM (tensor pipe, fp16 2-term, cp.async double-buffered)
// ===========================================================================
#define PJ_A    0
#define PJ_B0H  16384
#define PJ_B0L  24576
#define PJ_B1H  32768
#define PJ_B1L  40960
#define PJBUF   49152
#define OSTRIDE 132
#define P_TOTAL (2 * PJBUF)      // 98304

__global__ __launch_bounds__(256, 2) void proj_mma() {
    extern __shared__ char smem[];
    const uint32_t sb = smem_u32(smem);
    const int tid = threadIdx.x;
    const int w = tid >> 5, lane = tid & 31;
    const int b  = blockIdx.z;
    const int l0 = blockIdx.x * 128;
    const int o0 = blockIdx.y * 128;

    const int srow = tid >> 3, sch = tid & 7;
    const uint32_t sda = (uint32_t)(srow * 128 + sch * 16);
    const __half* pw  = g_whi + (size_t)(o0 + srow) * DD + sch * 8;
    const __half* pxh = g_xhi + ((size_t)b * DD + srow) * LL + l0 + sch * 8;
    const __half* pxl = g_xlo + ((size_t)b * DD + srow) * LL + l0 + sch * 8;

#define PREFETCH_PJ(stb) do { \
    cpa16((stb) + PJ_A + sda,          pw); \
    cpa16((stb) + PJ_A + sda + 4096,   pw + 32 * DD); \
    cpa16((stb) + PJ_A + sda + 8192,   pw + 64 * DD); \
    cpa16((stb) + PJ_A + sda + 12288,  pw + 96 * DD); \
    cpa16((stb) + PJ_B0H + sda,        pxh); \
    cpa16((stb) + PJ_B0H + sda + 4096, pxh + (size_t)32 * LL); \
    cpa16((stb) + PJ_B1H + sda,        pxh + 64); \
    cpa16((stb) + PJ_B1H + sda + 4096, pxh + (size_t)32 * LL + 64); \
    cpa16((stb) + PJ_B0L + sda,        pxl); \
    cpa16((stb) + PJ_B0L + sda + 4096, pxl + (size_t)32 * LL); \
    cpa16((stb) + PJ_B1L + sda,        pxl + 64); \
    cpa16((stb) + PJ_B1L + sda + 4096, pxl + (size_t)32 * LL + 64); \
    pw += 64; pxh += (size_t)64 * LL; pxl += (size_t)64 * LL; \
} while (0)

    PREFETCH_PJ(sb);
    CPA_COMMIT();

    const int mi     = lane >> 3;
    const int arow   = w * 16 + ((mi & 1) << 3) + (lane & 7);
    const int acolh  = (mi >> 1) * 16;
    const int b_ksub = ((mi & 1) << 3) + (lane & 7);
    const int b_noct = mi >> 1;

    // hoisted swizzle terms (row&7 constant per lane within each loop)
    const uint32_t arow128 = (uint32_t)(arow * 128);
    const uint32_t xva = (uint32_t)((arow & 7) << 4);
    const uint32_t xvb = (uint32_t)((b_ksub & 7) << 4);
    uint32_t ca[4], rbp[4], cbx[4];
    #pragma unroll
    for (int ks = 0; ks < 4; ks++) {
        ca[ks]  = (uint32_t)(ks * 32 + acolh) ^ xva;
        rbp[ks] = (uint32_t)((ks * 16 + b_ksub) * 128);
    }
    #pragma unroll
    for (int j2 = 0; j2 < 4; j2++)
        cbx[j2] = (uint32_t)((2 * j2 + b_noct) * 16) ^ xvb;

    float c[16][4];
    #pragma unroll
    for (int i = 0; i < 16; i++)
        #pragma unroll
        for (int j = 0; j < 4; j++) c[i][j] = 0.f;

    uint32_t bufc = sb, bufn = sb + PJBUF;
    for (int kc = 0; kc < 8; kc++) {
        CPA_WAIT(0);
        __syncthreads();
        if (kc + 1 < 8) {
            PREFETCH_PJ(bufn);
            CPA_COMMIT();
        }

        #pragma unroll
        for (int ks = 0; ks < 4; ks++) {
            uint32_t ahi[4];
            ldsm4(ahi, bufc + PJ_A + arow128 + ca[ks]);
            #pragma unroll
            for (int hb = 0; hb < 2; hb++) {
                const uint32_t bh = bufc + (hb ? PJ_B1H : PJ_B0H) + rbp[ks];
                const uint32_t bl = bufc + (hb ? PJ_B1L : PJ_B0L) + rbp[ks];
                #pragma unroll
                for (int j2 = 0; j2 < 4; j2++) {
                    uint32_t bhi[4], blo[4];
                    ldsm4t(bhi, bh + cbx[j2]);
                    ldsm4t(blo, bl + cbx[j2]);
                    const int o1 = hb * 8 + 2 * j2;
                    mma16816(c[o1],     ahi, bhi);
                    mma16816(c[o1],     ahi, blo);
                    mma16816(c[o1 + 1], ahi, bhi + 2);
                    mma16816(c[o1 + 1], ahi, blo + 2);
                }
            }
        }

        uint32_t t = bufc; bufc = bufn; bufn = t;
    }

    // ---- fragments -> smem [o][OSTRIDE] fp32 ----
    __syncthreads();
    float* Osm = (float*)smem;
    {
        const int r1 = w * 16 + (lane >> 2);
        const int cb = (lane & 3) << 1;
        #pragma unroll
        for (int oct = 0; oct < 16; oct++) {
            const int col = (oct >> 3) * 64 + (oct & 7) * 8 + cb;
            Osm[r1 * OSTRIDE + col]           = c[oct][0];
            Osm[r1 * OSTRIDE + col + 1]       = c[oct][1];
            Osm[(r1 + 8) * OSTRIDE + col]     = c[oct][2];
            Osm[(r1 + 8) * OSTRIDE + col + 1] = c[oct][3];
        }
    }
    __syncthreads();

    if (o0 >= 512 && o0 < 1024) {
        #pragma unroll
        for (int i = tid; i < 2048; i += 256) {
            int row = i >> 4, ch = i & 15;
            int vr = (o0 - 512) + row;
            const float* src = &Osm[row * OSTRIDE + ch * 8];
            __align__(16) __half hi8[8];
            #pragma unroll
            for (int k = 0; k < 8; k++)
                hi8[k] = __float2half_rn(src[k]);
            int seg = ch >> 3, pc = (ch & 7) ^ (vr & 7);
            size_t ge = ((size_t)b * DD + vr) * LL + l0 + seg * 64 + pc * 8;
            *(uint4*)&g_vhi[ge] = *(uint4*)hi8;
        }
    } else if (o0 < 512) {
        #pragma unroll
        for (int i = tid; i < 2048; i += 256) {
            int l = i >> 4, ch = i & 15;
            int gl = l0 + l;
            __align__(16) __half hi8[8];
            #pragma unroll
            for (int k = 0; k < 8; k++) {
                int rk = (k + lane) & 7;
                hi8[rk] = __float2half_rn(Osm[(ch * 8 + rk) * OSTRIDE + l]);
            }
            int seg = ch >> 3, pc = (ch & 7) ^ (gl & 7);
            size_t ge = ((size_t)b * LL + gl) * DD + o0 + seg * 64 + pc * 8;
            *(uint4*)&g_khi[ge] = *(uint4*)hi8;
        }
    } else {
        #pragma unroll
        for (int i = tid; i < 2048; i += 256) {
            int l = i >> 4, ch = i & 15;
            int gl = l0 + l;
            __align__(16) __half hi8[8];
            #pragma unroll
            for (int k = 0; k < 8; k++) {
                int rk = (k + lane) & 7;
                hi8[rk] = __float2half_rn(Osm[(ch * 8 + rk) * OSTRIDE + l] * 0.125f);
            }
            int seg = ch >> 3, pc = (ch & 7) ^ (gl & 7);
            size_t ge = ((size_t)b * LL + gl) * DD + (o0 - 1024) + seg * 64 + pc * 8;
            *(uint4*)&g_qhi[ge] = *(uint4*)hi8;
        }
    }
}

// ===========================================================================
// mma.sync flash attention (pure fp16), hoisted swizzle addressing,
// float-mask multiply, packed f16x2 converts.
// ===========================================================================
#define ST_SIZE  16640            // KHI 8K | VHI 8K | MSKF 256
#define SM_TOTAL (3 * ST_SIZE)    // 49920

__global__ __launch_bounds__(256, 2) void attn_mma(float* __restrict__ out)
{
    extern __shared__ char smem[];
    const uint32_t sb = smem_u32(smem);
    const int tid  = threadIdx.x;
    const int w    = tid >> 5;
    const int lane = tid & 31;
    const int b = blockIdx.z, h = blockIdx.y, q0 = blockIdx.x * 128;

    const size_t qkrow0 = (size_t)b * LL * DD + (size_t)h * 64;
    const size_t vrow0  = ((size_t)b * DD + h * 64) * LL;

    const int srow = tid >> 3;
    const int sch  = tid & 7;
    const uint32_t sd = (uint32_t)(srow * 128 + sch * 16);

    const __half* pkh = g_khi + qkrow0 + (size_t)srow * DD + sch * 8;
    const __half* pvh = g_vhi + vrow0 + (size_t)srow * LL + sch * 8;
    const float*  pmk = g_mkf + (size_t)b * LL + tid * 4;

#define PREFETCH_TILE(stb) do { \
    cpa16((stb) + sd,                pkh); \
    cpa16((stb) + sd + 4096,         pkh + 32 * DD); \
    cpa16((stb) + 8192 + sd,         pvh); \
    cpa16((stb) + 8192 + sd + 4096,  pvh + (size_t)32 * LL); \
    if (tid < 16) cpa16((stb) + 16384 + tid * 16, pmk); \
    pkh += 64 * DD; pvh += 64; pmk += 64; \
} while (0)

    {
        const __half* pq = g_qhi + qkrow0 + (size_t)(q0 + srow) * DD + sch * 8;
        const uint32_t qst = sb + 2 * ST_SIZE;
        cpa16(qst + sd,          pq);
        cpa16(qst + sd + 4096,   pq + 32 * DD);
        cpa16(qst + sd + 8192,   pq + 64 * DD);
        cpa16(qst + sd + 12288,  pq + 96 * DD);
        CPA_COMMIT();
    }
    PREFETCH_TILE(sb);             CPA_COMMIT();
    PREFETCH_TILE(sb + ST_SIZE);   CPA_COMMIT();

    const int mi = lane >> 3;
    const int qrow_l = w * 16 + ((mi & 1) << 3) + (lane & 7);
    const int a_colh = (mi >> 1) * 16;
    const int b_rsub = ((mi >> 1) << 3) + (lane & 7);
    const int b_colh = (mi & 1) * 16;

    // hoisted swizzle terms for K/V B-fragments (row&7 = b_rsub&7, const)
    const uint32_t xv = (uint32_t)((b_rsub & 7) << 4);
    uint32_t rb[4], cx[4];
    #pragma unroll
    for (int j2 = 0; j2 < 4; j2++)
        rb[j2] = (uint32_t)((j2 * 16 + b_rsub) * 128);
    #pragma unroll
    for (int kc = 0; kc < 4; kc++)
        cx[kc] = (uint32_t)(kc * 32 + b_colh) ^ xv;

    CPA_WAIT(2);
    __syncthreads();
    uint32_t qf[4][4];
    {
        const uint32_t qb2 = sb + 2 * ST_SIZE;
        #pragma unroll
        for (int kc = 0; kc < 4; kc++) {
            uint32_t qoff = (uint32_t)(qrow_l * 128 + kc * 32 + a_colh);
            ldsm4(qf[kc], qb2 + SWZ128(qoff));
        }
    }
    __syncthreads();

    float o_acc[8][4];
    #pragma unroll
    for (int i = 0; i < 8; i++)
        #pragma unroll
        for (int j = 0; j < 4; j++) o_acc[i][j] = 0.f;
    float lsum0 = 0.f, lsum1 = 0.f;

    uint32_t stc = sb;
    uint32_t stn = sb + 2 * ST_SIZE;

    for (int it = 0; it < 32; it++) {
        if (it == 31) { CPA_WAIT(0); } else { CPA_WAIT(1); }
        __syncthreads();

        if (it + 2 < 32) {
            PREFETCH_TILE(stn);
            CPA_COMMIT();
            stn = (stn == sb + 2 * ST_SIZE) ? sb : stn + ST_SIZE;
        }

        const uint32_t kh = stc, vh = stc + 8192;
        const float* mpf = (const float*)(smem + (stc - sb) + 16384);

        // ---- S = Q_hi.K_hi^T ----
        float s[8][4];
        #pragma unroll
        for (int i = 0; i < 8; i++)
            #pragma unroll
            for (int j = 0; j < 4; j++) s[i][j] = 0.f;

        #pragma unroll
        for (int kc = 0; kc < 4; kc++) {
            #pragma unroll
            for (int j2 = 0; j2 < 4; j2++) {
                uint32_t bhi[4];
                ldsm4(bhi, kh + rb[j2] + cx[kc]);
                mma16816(s[2 * j2],     qf[kc], bhi);
                mma16816(s[2 * j2 + 1], qf[kc], bhi + 2);
            }
        }

        // ---- softmax: p = exp(s) * mask_float ----
        uint32_t phiA[8], phiB[8];
        const int cb2 = (lane & 3) << 1;
        #pragma unroll
        for (int nt = 0; nt < 8; nt++) {
            float2 mf = *(const float2*)&mpf[nt * 8 + cb2];
            float p0 = __expf(s[nt][0]) * mf.x;
            float p1 = __expf(s[nt][1]) * mf.y;
            float p2 = __expf(s[nt][2]) * mf.x;
            float p3 = __expf(s[nt][3]) * mf.y;
            lsum0 += p0 + p1;
            lsum1 += p2 + p3;
            phiA[nt] = pack_h2(p0, p1);
            phiB[nt] = pack_h2(p2, p3);
        }

        // ---- O += P_hi.V_hi ----
        #pragma unroll
        for (int kc = 0; kc < 4; kc++) {
            uint32_t ahi[4] = {phiA[2 * kc], phiB[2 * kc], phiA[2 * kc + 1], phiB[2 * kc + 1]};
            #pragma unroll
            for (int j2 = 0; j2 < 4; j2++) {
                uint32_t bhi[4];
                ldsm4(bhi, vh + rb[j2] + cx[kc]);
                mma16816(o_acc[2 * j2],     ahi, bhi);
                mma16816(o_acc[2 * j2 + 1], ahi, bhi + 2);
            }
        }

        stc = (stc == sb + 2 * ST_SIZE) ? sb : stc + ST_SIZE;
    }

    __syncthreads();

    #pragma unroll
    for (int off = 1; off < 4; off <<= 1) {
        lsum0 += __shfl_xor_sync(0xffffffffu, lsum0, off);
        lsum1 += __shfl_xor_sync(0xffffffffu, lsum1, off);
    }
    const float inv0 = 1.0f / lsum0, inv1 = 1.0f / lsum1;

    float* Osm = (float*)smem;
    const int r1 = w * 16 + (lane >> 2);
    const int cb = (lane & 3) << 1;
    #pragma unroll
    for (int nt = 0; nt < 8; nt++) {
        const int c0 = nt * 8 + cb;
        Osm[r1 * 66 + c0]           = o_acc[nt][0] * inv0;
        Osm[r1 * 66 + c0 + 1]       = o_acc[nt][1] * inv0;
        Osm[(r1 + 8) * 66 + c0]     = o_acc[nt][2] * inv1;
        Osm[(r1 + 8) * 66 + c0 + 1] = o_acc[nt][3] * inv1;
    }
    __syncthreads();
    {
        const int dh = tid >> 2;
        const int qc = (tid & 3) << 5;
        float* op = out + ((size_t)b * DD + h * 64 + dh) * LL + q0 + qc;
        #pragma unroll
        for (int i = 0; i < 8; i++) {
            float4 v = make_float4(Osm[(qc + 4 * i + 0) * 66 + dh],
                                   Osm[(qc + 4 * i + 1) * 66 + dh],
                                   Osm[(qc + 4 * i + 2) * 66 + dh],
                                   Osm[(qc + 4 * i + 3) * 66 + dh]);
            *(float4*)(op + 4 * i) = v;
        }
    }
}

// ===========================================================================
extern "C" void kernel_launch(void* const* d_in, const int* in_sizes, int n_in,
                              void* d_out, int out_size) {
    (void)in_sizes; (void)n_in; (void)out_size;
    const float* queries = (const float*)d_in[0];
    const int*   mask    = (const int*)d_in[1];
    const float* w_mem   = (const float*)d_in[2];
    const float* w_q     = (const float*)d_in[3];
    float* out = (float*)d_out;

    cvt_w<<<384, 256>>>(w_mem, w_q);
    cvt_q<<<4096, 256>>>(queries);
    cvt_m<<<64, 256>>>(mask);

    cudaFuncSetAttribute(proj_mma, cudaFuncAttributeMaxDynamicSharedMemorySize, P_TOTAL);
    dim3 gp(LL / 128, 1536 / 128, BB);
    proj_mma<<<gp, 256, P_TOTAL>>>();

    cudaFuncSetAttribute(attn_mma, cudaFuncAttributeMaxDynamicSharedMemorySize, SM_TOTAL);
    dim3 ga(LL / 128, HH, BB);
    attn_mma<<<ga, 256, SM_TOTAL>>>(out);
}

// round 14
// speedup vs baseline: 1.4854x; 1.4854x over previous
#include <cuda_runtime.h>
#include <cuda_fp16.h>
#include <cstdint>
#include <math.h>

#define BB 8
#define DD 512
#define LL 2048
#define HH 8

// fp16 scratch, all pre-swizzled (SW128 chunk perm by row&7 within 64-elem segs)
__device__ __half g_qhi[(size_t)BB * LL * DD];            // [b][l][512] (attn Q)
__device__ __half g_khi[(size_t)BB * LL * DD];            // [b][l][512] (attn K)
__device__ __half g_vhi[(size_t)BB * DD * LL];            // [b][dh][l]  (attn V)
__device__ __half g_whi[(size_t)1536 * DD];               // [o][512]    (proj A, hi)
__device__ __half g_xhi[(size_t)BB * DD * LL];            // [b][d][l]   (proj B hi)
__device__ __half g_xlo[(size_t)BB * DD * LL];            // [b][d][l]   (proj B lo)
__device__ float  g_mkf[(size_t)BB * LL];                 // mask as float {0,1}

// ============================ helpers ======================================
__device__ __forceinline__ uint32_t smem_u32(const void* p) {
    uint32_t a;
    asm("{ .reg .u64 t; cvta.to.shared.u64 t, %1; cvt.u32.u64 %0, t; }"
        : "=r"(a) : "l"(p));
    return a;
}

#define SWZ128(off) ((off) ^ (((off) >> 3) & 0x70))

__device__ __forceinline__ void ldsm4(uint32_t* r, uint32_t addr) {
    asm volatile("ldmatrix.sync.aligned.m8n8.x4.shared.b16 {%0,%1,%2,%3}, [%4];"
        : "=r"(r[0]), "=r"(r[1]), "=r"(r[2]), "=r"(r[3]) : "r"(addr));
}

__device__ __forceinline__ void ldsm4t(uint32_t* r, uint32_t addr) {
    asm volatile("ldmatrix.sync.aligned.m8n8.x4.trans.shared.b16 {%0,%1,%2,%3}, [%4];"
        : "=r"(r[0]), "=r"(r[1]), "=r"(r[2]), "=r"(r[3]) : "r"(addr));
}

__device__ __forceinline__ void mma16816(float* d, const uint32_t* a, const uint32_t* b) {
    asm volatile("mma.sync.aligned.m16n8k16.row.col.f32.f16.f16.f32 "
        "{%0,%1,%2,%3}, {%4,%5,%6,%7}, {%8,%9}, {%0,%1,%2,%3};"
        : "+f"(d[0]), "+f"(d[1]), "+f"(d[2]), "+f"(d[3])
        : "r"(a[0]), "r"(a[1]), "r"(a[2]), "r"(a[3]), "r"(b[0]), "r"(b[1]));
}

__device__ __forceinline__ void cpa16(uint32_t sdst, const void* gsrc) {
    asm volatile("cp.async.cg.shared.global [%0], [%1], 16;"
        :: "r"(sdst), "l"(gsrc));
}
#define CPA_COMMIT() asm volatile("cp.async.commit_group;" ::: "memory")
#define CPA_WAIT(n)  asm volatile("cp.async.wait_group %0;" :: "n"(n) : "memory")

// pack two fp32 into one half2 reg: {lo=a, hi=b}
__device__ __forceinline__ uint32_t pack_h2(float a, float b) {
    uint32_t r;
    asm("cvt.rn.f16x2.f32 %0, %1, %2;" : "=r"(r) : "f"(b), "f"(a));
    return r;
}

// ===========================================================================
// One-shot conversion kernels (fp32/int -> pre-swizzled fp16/float gmem)
// ===========================================================================
__global__ void cvt_w(const float* __restrict__ w_mem, const float* __restrict__ w_q) {
    int idx = blockIdx.x * 256 + threadIdx.x;     // 1536*64
    int o = idx >> 6, ch = idx & 63;
    int seg = ch >> 3, c8 = ch & 7;
    const float* src = (o < 1024 ? w_mem + (size_t)o * DD
                                 : w_q + (size_t)(o - 1024) * DD) + seg * 64 + c8 * 8;
    float4 v0 = *(const float4*)src, v1 = *(const float4*)(src + 4);
    __align__(16) __half h8[8];
    h8[0] = __float2half_rn(v0.x); h8[1] = __float2half_rn(v0.y);
    h8[2] = __float2half_rn(v0.z); h8[3] = __float2half_rn(v0.w);
    h8[4] = __float2half_rn(v1.x); h8[5] = __float2half_rn(v1.y);
    h8[6] = __float2half_rn(v1.z); h8[7] = __float2half_rn(v1.w);
    int pc = c8 ^ (o & 7);
    *(uint4*)&g_whi[(size_t)o * DD + seg * 64 + pc * 8] = *(uint4*)h8;
}

__global__ void cvt_q(const float* __restrict__ qin) {
    int idx = blockIdx.x * 256 + threadIdx.x;     // 8*512*256
    int b = idx >> 17;
    int r = idx & 131071;
    int d = r >> 8, ch = r & 255;
    int seg = ch >> 3, c8 = ch & 7;
    size_t base = ((size_t)b * DD + d) * LL;
    const float* src = qin + base + seg * 64 + c8 * 8;
    float4 v0 = *(const float4*)src, v1 = *(const float4*)(src + 4);
    __align__(16) __half hi8[8], lo8[8];
    float vv[8] = {v0.x, v0.y, v0.z, v0.w, v1.x, v1.y, v1.z, v1.w};
    #pragma unroll
    for (int k = 0; k < 8; k++) {
        __half hx = __float2half_rn(vv[k]);
        hi8[k] = hx;
        lo8[k] = __float2half_rn(vv[k] - __half2float(hx));
    }
    int pc = c8 ^ (d & 7);
    size_t ge = base + seg * 64 + pc * 8;
    *(uint4*)&g_xhi[ge] = *(uint4*)hi8;
    *(uint4*)&g_xlo[ge] = *(uint4*)lo8;
}

__global__ void cvt_m(const int* __restrict__ mask) {
    int i = blockIdx.x * 256 + threadIdx.x;       // 16384
    g_mkf[i] = (float)mask[i];
}

// ===========================================================================
// Projection GEMM (exact Round-12 version: inline SWZ, no hoisted arrays)
// ===========================================================================
#define PJ_A    0
#define PJ_B0H  16384
#define PJ_B0L  24576
#define PJ_B1H  32768
#define PJ_B1L  40960
#define PJBUF   49152
#define OSTRIDE 132
#define P_TOTAL (2 * PJBUF)      // 98304

__global__ __launch_bounds__(256, 2) void proj_mma() {
    extern __shared__ char smem[];
    const uint32_t sb = smem_u32(smem);
    const int tid = threadIdx.x;
    const int w = tid >> 5, lane = tid & 31;
    const int b  = blockIdx.z;
    const int l0 = blockIdx.x * 128;
    const int o0 = blockIdx.y * 128;

    const int srow = tid >> 3, sch = tid & 7;
    const uint32_t sda = (uint32_t)(srow * 128 + sch * 16);
    const __half* pw  = g_whi + (size_t)(o0 + srow) * DD + sch * 8;
    const __half* pxh = g_xhi + ((size_t)b * DD + srow) * LL + l0 + sch * 8;
    const __half* pxl = g_xlo + ((size_t)b * DD + srow) * LL + l0 + sch * 8;

#define PREFETCH_PJ(stb) do { \
    cpa16((stb) + PJ_A + sda,          pw); \
    cpa16((stb) + PJ_A + sda + 4096,   pw + 32 * DD); \
    cpa16((stb) + PJ_A + sda + 8192,   pw + 64 * DD); \
    cpa16((stb) + PJ_A + sda + 12288,  pw + 96 * DD); \
    cpa16((stb) + PJ_B0H + sda,        pxh); \
    cpa16((stb) + PJ_B0H + sda + 4096, pxh + (size_t)32 * LL); \
    cpa16((stb) + PJ_B1H + sda,        pxh + 64); \
    cpa16((stb) + PJ_B1H + sda + 4096, pxh + (size_t)32 * LL + 64); \
    cpa16((stb) + PJ_B0L + sda,        pxl); \
    cpa16((stb) + PJ_B0L + sda + 4096, pxl + (size_t)32 * LL); \
    cpa16((stb) + PJ_B1L + sda,        pxl + 64); \
    cpa16((stb) + PJ_B1L + sda + 4096, pxl + (size_t)32 * LL + 64); \
    pw += 64; pxh += (size_t)64 * LL; pxl += (size_t)64 * LL; \
} while (0)

    PREFETCH_PJ(sb);
    CPA_COMMIT();

    const int mi     = lane >> 3;
    const int arow   = w * 16 + ((mi & 1) << 3) + (lane & 7);
    const int acolh  = (mi >> 1) * 16;
    const int b_ksub = ((mi & 1) << 3) + (lane & 7);
    const int b_noct = mi >> 1;

    float c[16][4];
    #pragma unroll
    for (int i = 0; i < 16; i++)
        #pragma unroll
        for (int j = 0; j < 4; j++) c[i][j] = 0.f;

    uint32_t bufc = sb, bufn = sb + PJBUF;
    for (int kc = 0; kc < 8; kc++) {
        CPA_WAIT(0);
        __syncthreads();
        if (kc + 1 < 8) {
            PREFETCH_PJ(bufn);
            CPA_COMMIT();
        }

        #pragma unroll
        for (int ks = 0; ks < 4; ks++) {
            uint32_t ahi[4];
            uint32_t aoff = (uint32_t)(arow * 128 + ks * 32 + acolh);
            ldsm4(ahi, bufc + PJ_A + SWZ128(aoff));
            #pragma unroll
            for (int hb = 0; hb < 2; hb++) {
                const uint32_t bh = bufc + (hb ? PJ_B1H : PJ_B0H);
                const uint32_t bl = bufc + (hb ? PJ_B1L : PJ_B0L);
                #pragma unroll
                for (int j = 0; j < 8; j += 2) {
                    uint32_t boff = (uint32_t)((ks * 16 + b_ksub) * 128 + (j + b_noct) * 16);
                    uint32_t bhi[4], blo[4];
                    ldsm4t(bhi, bh + SWZ128(boff));
                    ldsm4t(blo, bl + SWZ128(boff));
                    const int o1 = hb * 8 + j;
                    mma16816(c[o1],     ahi, bhi);
                    mma16816(c[o1],     ahi, blo);
                    mma16816(c[o1 + 1], ahi, bhi + 2);
                    mma16816(c[o1 + 1], ahi, blo + 2);
                }
            }
        }

        uint32_t t = bufc; bufc = bufn; bufn = t;
    }

    // ---- fragments -> smem [o][OSTRIDE] fp32 ----
    __syncthreads();
    float* Osm = (float*)smem;
    {
        const int r1 = w * 16 + (lane >> 2);
        const int cb = (lane & 3) << 1;
        #pragma unroll
        for (int oct = 0; oct < 16; oct++) {
            const int col = (oct >> 3) * 64 + (oct & 7) * 8 + cb;
            Osm[r1 * OSTRIDE + col]           = c[oct][0];
            Osm[r1 * OSTRIDE + col + 1]       = c[oct][1];
            Osm[(r1 + 8) * OSTRIDE + col]     = c[oct][2];
            Osm[(r1 + 8) * OSTRIDE + col + 1] = c[oct][3];
        }
    }
    __syncthreads();

    if (o0 >= 512 && o0 < 1024) {
        #pragma unroll
        for (int i = tid; i < 2048; i += 256) {
            int row = i >> 4, ch = i & 15;
            int vr = (o0 - 512) + row;
            const float* src = &Osm[row * OSTRIDE + ch * 8];
            __align__(16) __half hi8[8];
            #pragma unroll
            for (int k = 0; k < 8; k++)
                hi8[k] = __float2half_rn(src[k]);
            int seg = ch >> 3, pc = (ch & 7) ^ (vr & 7);
            size_t ge = ((size_t)b * DD + vr) * LL + l0 + seg * 64 + pc * 8;
            *(uint4*)&g_vhi[ge] = *(uint4*)hi8;
        }
    } else if (o0 < 512) {
        #pragma unroll
        for (int i = tid; i < 2048; i += 256) {
            int l = i >> 4, ch = i & 15;
            int gl = l0 + l;
            __align__(16) __half hi8[8];
            #pragma unroll
            for (int k = 0; k < 8; k++) {
                int rk = (k + lane) & 7;
                hi8[rk] = __float2half_rn(Osm[(ch * 8 + rk) * OSTRIDE + l]);
            }
            int seg = ch >> 3, pc = (ch & 7) ^ (gl & 7);
            size_t ge = ((size_t)b * LL + gl) * DD + o0 + seg * 64 + pc * 8;
            *(uint4*)&g_khi[ge] = *(uint4*)hi8;
        }
    } else {
        #pragma unroll
        for (int i = tid; i < 2048; i += 256) {
            int l = i >> 4, ch = i & 15;
            int gl = l0 + l;
            __align__(16) __half hi8[8];
            #pragma unroll
            for (int k = 0; k < 8; k++) {
                int rk = (k + lane) & 7;
                hi8[rk] = __float2half_rn(Osm[(ch * 8 + rk) * OSTRIDE + l] * 0.125f);
            }
            int seg = ch >> 3, pc = (ch & 7) ^ (gl & 7);
            size_t ge = ((size_t)b * LL + gl) * DD + (o0 - 1024) + seg * 64 + pc * 8;
            *(uint4*)&g_qhi[ge] = *(uint4*)hi8;
        }
    }
}

// ===========================================================================
// mma.sync flash attention: Round-12 structure (inline SWZ addressing),
// plus register-neutral softmax: float-mask multiply + packed f16x2 cvt.
// ===========================================================================
#define ST_SIZE  16640            // KHI 8K | VHI 8K | MSKF 256
#define SM_TOTAL (3 * ST_SIZE)    // 49920

__global__ __launch_bounds__(256, 2) void attn_mma(float* __restrict__ out)
{
    extern __shared__ char smem[];
    const uint32_t sb = smem_u32(smem);
    const int tid  = threadIdx.x;
    const int w    = tid >> 5;
    const int lane = tid & 31;
    const int b = blockIdx.z, h = blockIdx.y, q0 = blockIdx.x * 128;

    const size_t qkrow0 = (size_t)b * LL * DD + (size_t)h * 64;
    const size_t vrow0  = ((size_t)b * DD + h * 64) * LL;

    const int srow = tid >> 3;
    const int sch  = tid & 7;
    const uint32_t sd = (uint32_t)(srow * 128 + sch * 16);

    const __half* pkh = g_khi + qkrow0 + (size_t)srow * DD + sch * 8;
    const __half* pvh = g_vhi + vrow0 + (size_t)srow * LL + sch * 8;
    const float*  pmk = g_mkf + (size_t)b * LL + tid * 4;

#define PREFETCH_TILE(stb) do { \
    cpa16((stb) + sd,                pkh); \
    cpa16((stb) + sd + 4096,         pkh + 32 * DD); \
    cpa16((stb) + 8192 + sd,         pvh); \
    cpa16((stb) + 8192 + sd + 4096,  pvh + (size_t)32 * LL); \
    if (tid < 16) cpa16((stb) + 16384 + tid * 16, pmk); \
    pkh += 64 * DD; pvh += 64; pmk += 64; \
} while (0)

    {
        const __half* pq = g_qhi + qkrow0 + (size_t)(q0 + srow) * DD + sch * 8;
        const uint32_t qst = sb + 2 * ST_SIZE;
        cpa16(qst + sd,          pq);
        cpa16(qst + sd + 4096,   pq + 32 * DD);
        cpa16(qst + sd + 8192,   pq + 64 * DD);
        cpa16(qst + sd + 12288,  pq + 96 * DD);
        CPA_COMMIT();
    }
    PREFETCH_TILE(sb);             CPA_COMMIT();
    PREFETCH_TILE(sb + ST_SIZE);   CPA_COMMIT();

    const int mi = lane >> 3;
    const int qrow_l = w * 16 + ((mi & 1) << 3) + (lane & 7);
    const int a_colh = (mi >> 1) * 16;
    const int b_rsub = ((mi >> 1) << 3) + (lane & 7);
    const int b_colh = (mi & 1) * 16;

    CPA_WAIT(2);
    __syncthreads();
    uint32_t qf[4][4];
    {
        const uint32_t qb2 = sb + 2 * ST_SIZE;
        #pragma unroll
        for (int kc = 0; kc < 4; kc++) {
            uint32_t qoff = (uint32_t)(qrow_l * 128 + kc * 32 + a_colh);
            ldsm4(qf[kc], qb2 + SWZ128(qoff));
        }
    }
    __syncthreads();

    float o_acc[8][4];
    #pragma unroll
    for (int i = 0; i < 8; i++)
        #pragma unroll
        for (int j = 0; j < 4; j++) o_acc[i][j] = 0.f;
    float lsum0 = 0.f, lsum1 = 0.f;

    uint32_t stc = sb;
    uint32_t stn = sb + 2 * ST_SIZE;

    for (int it = 0; it < 32; it++) {
        if (it == 31) { CPA_WAIT(0); } else { CPA_WAIT(1); }
        __syncthreads();

        if (it + 2 < 32) {
            PREFETCH_TILE(stn);
            CPA_COMMIT();
            stn = (stn == sb + 2 * ST_SIZE) ? sb : stn + ST_SIZE;
        }

        const uint32_t kh = stc, vh = stc + 8192;
        const float* mpf = (const float*)(smem + (stc - sb) + 16384);

        // ---- S = Q_hi.K_hi^T ----
        float s[8][4];
        #pragma unroll
        for (int i = 0; i < 8; i++)
            #pragma unroll
            for (int j = 0; j < 4; j++) s[i][j] = 0.f;

        #pragma unroll
        for (int kc = 0; kc < 4; kc++) {
            #pragma unroll
            for (int j = 0; j < 8; j += 2) {
                uint32_t bhi[4];
                uint32_t koff = (uint32_t)((j * 8 + b_rsub) * 128 + kc * 32 + b_colh);
                ldsm4(bhi, kh + SWZ128(koff));
                mma16816(s[j],     qf[kc], bhi);
                mma16816(s[j + 1], qf[kc], bhi + 2);
            }
        }

        // ---- softmax: p = exp(s) * mask_float; packed f16x2 converts ----
        uint32_t phiA[8], phiB[8];
        const int cb2 = (lane & 3) << 1;
        #pragma unroll
        for (int nt = 0; nt < 8; nt++) {
            float2 mf = *(const float2*)&mpf[nt * 8 + cb2];
            float p0 = __expf(s[nt][0]) * mf.x;
            float p1 = __expf(s[nt][1]) * mf.y;
            float p2 = __expf(s[nt][2]) * mf.x;
            float p3 = __expf(s[nt][3]) * mf.y;
            lsum0 += p0 + p1;
            lsum1 += p2 + p3;
            phiA[nt] = pack_h2(p0, p1);
            phiB[nt] = pack_h2(p2, p3);
        }

        // ---- O += P_hi.V_hi ----
        #pragma unroll
        for (int kc = 0; kc < 4; kc++) {
            uint32_t ahi[4] = {phiA[2 * kc], phiB[2 * kc], phiA[2 * kc + 1], phiB[2 * kc + 1]};
            #pragma unroll
            for (int j = 0; j < 8; j += 2) {
                uint32_t bhi[4];
                uint32_t voff = (uint32_t)((j * 8 + b_rsub) * 128 + kc * 32 + b_colh);
                ldsm4(bhi, vh + SWZ128(voff));
                mma16816(o_acc[j],     ahi, bhi);
                mma16816(o_acc[j + 1], ahi, bhi + 2);
            }
        }

        stc = (stc == sb + 2 * ST_SIZE) ? sb : stc + ST_SIZE;
    }

    __syncthreads();

    #pragma unroll
    for (int off = 1; off < 4; off <<= 1) {
        lsum0 += __shfl_xor_sync(0xffffffffu, lsum0, off);
        lsum1 += __shfl_xor_sync(0xffffffffu, lsum1, off);
    }
    const float inv0 = 1.0f / lsum0, inv1 = 1.0f / lsum1;

    float* Osm = (float*)smem;
    const int r1 = w * 16 + (lane >> 2);
    const int cb = (lane & 3) << 1;
    #pragma unroll
    for (int nt = 0; nt < 8; nt++) {
        const int c0 = nt * 8 + cb;
        Osm[r1 * 66 + c0]           = o_acc[nt][0] * inv0;
        Osm[r1 * 66 + c0 + 1]       = o_acc[nt][1] * inv0;
        Osm[(r1 + 8) * 66 + c0]     = o_acc[nt][2] * inv1;
        Osm[(r1 + 8) * 66 + c0 + 1] = o_acc[nt][3] * inv1;
    }
    __syncthreads();
    {
        const int dh = tid >> 2;
        const int qc = (tid & 3) << 5;
        float* op = out + ((size_t)b * DD + h * 64 + dh) * LL + q0 + qc;
        #pragma unroll
        for (int i = 0; i < 8; i++) {
            float4 v = make_float4(Osm[(qc + 4 * i + 0) * 66 + dh],
                                   Osm[(qc + 4 * i + 1) * 66 + dh],
                                   Osm[(qc + 4 * i + 2) * 66 + dh],
                                   Osm[(qc + 4 * i + 3) * 66 + dh]);
            *(float4*)(op + 4 * i) = v;
        }
    }
}

// ===========================================================================
extern "C" void kernel_launch(void* const* d_in, const int* in_sizes, int n_in,
                              void* d_out, int out_size) {
    (void)in_sizes; (void)n_in; (void)out_size;
    const float* queries = (const float*)d_in[0];
    const int*   mask    = (const int*)d_in[1];
    const float* w_mem   = (const float*)d_in[2];
    const float* w_q     = (const float*)d_in[3];
    float* out = (float*)d_out;

    cvt_w<<<384, 256>>>(w_mem, w_q);
    cvt_q<<<4096, 256>>>(queries);
    cvt_m<<<64, 256>>>(mask);

    cudaFuncSetAttribute(proj_mma, cudaFuncAttributeMaxDynamicSharedMemorySize, P_TOTAL);
    dim3 gp(LL / 128, 1536 / 128, BB);
    proj_mma<<<gp, 256, P_TOTAL>>>();

    cudaFuncSetAttribute(attn_mma, cudaFuncAttributeMaxDynamicSharedMemorySize, SM_TOTAL);
    dim3 ga(LL / 128, HH, BB);
    attn_mma<<<ga, 256, SM_TOTAL>>>(out);
}

// round 15
// speedup vs baseline: 1.6719x; 1.1255x over previous
#include <cuda_runtime.h>
#include <cuda_fp16.h>
#include <cstdint>
#include <math.h>

#define BB 8
#define DD 512
#define LL 2048
#define HH 8

// fp16 scratch, all pre-swizzled (SW128 chunk perm by row&7 within 64-elem segs)
__device__ __half g_qhi[(size_t)BB * LL * DD];            // [b][l][512] (attn Q)
__device__ __half g_khi[(size_t)BB * LL * DD];            // [b][l][512] (attn K)
__device__ __half g_vhi[(size_t)BB * DD * LL];            // [b][dh][l]  (attn V)
__device__ __half g_whi[(size_t)1536 * DD];               // [o][512]    (proj A)
__device__ __half g_xhi[(size_t)BB * DD * LL];            // [b][d][l]   (proj B)
__device__ float  g_mkf[(size_t)BB * LL];                 // mask as float {0,1}

// ============================ helpers ======================================
__device__ __forceinline__ uint32_t smem_u32(const void* p) {
    uint32_t a;
    asm("{ .reg .u64 t; cvta.to.shared.u64 t, %1; cvt.u32.u64 %0, t; }"
        : "=r"(a) : "l"(p));
    return a;
}

#define SWZ128(off) ((off) ^ (((off) >> 3) & 0x70))

__device__ __forceinline__ void ldsm4(uint32_t* r, uint32_t addr) {
    asm volatile("ldmatrix.sync.aligned.m8n8.x4.shared.b16 {%0,%1,%2,%3}, [%4];"
        : "=r"(r[0]), "=r"(r[1]), "=r"(r[2]), "=r"(r[3]) : "r"(addr));
}

__device__ __forceinline__ void ldsm4t(uint32_t* r, uint32_t addr) {
    asm volatile("ldmatrix.sync.aligned.m8n8.x4.trans.shared.b16 {%0,%1,%2,%3}, [%4];"
        : "=r"(r[0]), "=r"(r[1]), "=r"(r[2]), "=r"(r[3]) : "r"(addr));
}

__device__ __forceinline__ void mma16816(float* d, const uint32_t* a, const uint32_t* b) {
    asm volatile("mma.sync.aligned.m16n8k16.row.col.f32.f16.f16.f32 "
        "{%0,%1,%2,%3}, {%4,%5,%6,%7}, {%8,%9}, {%0,%1,%2,%3};"
        : "+f"(d[0]), "+f"(d[1]), "+f"(d[2]), "+f"(d[3])
        : "r"(a[0]), "r"(a[1]), "r"(a[2]), "r"(a[3]), "r"(b[0]), "r"(b[1]));
}

__device__ __forceinline__ void cpa16(uint32_t sdst, const void* gsrc) {
    asm volatile("cp.async.cg.shared.global [%0], [%1], 16;"
        :: "r"(sdst), "l"(gsrc));
}
#define CPA_COMMIT() asm volatile("cp.async.commit_group;" ::: "memory")
#define CPA_WAIT(n)  asm volatile("cp.async.wait_group %0;" :: "n"(n) : "memory")

// pack two fp32 into one half2 reg: {lo=a, hi=b}
__device__ __forceinline__ uint32_t pack_h2(float a, float b) {
    uint32_t r;
    asm("cvt.rn.f16x2.f32 %0, %1, %2;" : "=r"(r) : "f"(b), "f"(a));
    return r;
}

// ===========================================================================
// One-shot conversion kernels (fp32/int -> pre-swizzled fp16/float gmem)
// ===========================================================================
__global__ void cvt_w(const float* __restrict__ w_mem, const float* __restrict__ w_q) {
    int idx = blockIdx.x * 256 + threadIdx.x;     // 1536*64
    int o = idx >> 6, ch = idx & 63;
    int seg = ch >> 3, c8 = ch & 7;
    const float* src = (o < 1024 ? w_mem + (size_t)o * DD
                                 : w_q + (size_t)(o - 1024) * DD) + seg * 64 + c8 * 8;
    float4 v0 = *(const float4*)src, v1 = *(const float4*)(src + 4);
    __align__(16) __half h8[8];
    h8[0] = __float2half_rn(v0.x); h8[1] = __float2half_rn(v0.y);
    h8[2] = __float2half_rn(v0.z); h8[3] = __float2half_rn(v0.w);
    h8[4] = __float2half_rn(v1.x); h8[5] = __float2half_rn(v1.y);
    h8[6] = __float2half_rn(v1.z); h8[7] = __float2half_rn(v1.w);
    int pc = c8 ^ (o & 7);
    *(uint4*)&g_whi[(size_t)o * DD + seg * 64 + pc * 8] = *(uint4*)h8;
}

__global__ void cvt_q(const float* __restrict__ qin) {
    int idx = blockIdx.x * 256 + threadIdx.x;     // 8*512*256
    int b = idx >> 17;
    int r = idx & 131071;
    int d = r >> 8, ch = r & 255;
    int seg = ch >> 3, c8 = ch & 7;
    size_t base = ((size_t)b * DD + d) * LL;
    const float* src = qin + base + seg * 64 + c8 * 8;
    float4 v0 = *(const float4*)src, v1 = *(const float4*)(src + 4);
    __align__(16) __half hi8[8];
    hi8[0] = __float2half_rn(v0.x); hi8[1] = __float2half_rn(v0.y);
    hi8[2] = __float2half_rn(v0.z); hi8[3] = __float2half_rn(v0.w);
    hi8[4] = __float2half_rn(v1.x); hi8[5] = __float2half_rn(v1.y);
    hi8[6] = __float2half_rn(v1.z); hi8[7] = __float2half_rn(v1.w);
    int pc = c8 ^ (d & 7);
    *(uint4*)&g_xhi[base + seg * 64 + pc * 8] = *(uint4*)hi8;
}

__global__ void cvt_m(const int* __restrict__ mask) {
    int i = blockIdx.x * 256 + threadIdx.x;       // 16384
    g_mkf[i] = (float)mask[i];
}

// ===========================================================================
// Projection GEMM (pure fp16 hi.hi, triple-buffered cp.async, 2-deep prefetch)
//   out2[o][l] = sum_d W_hi[o][d] * x_hi[d][l]
// ===========================================================================
#define PJ_A    0
#define PJ_B0   16384
#define PJ_B1   24576
#define PJBUF   32768
#define OSTRIDE 132
#define P_TOTAL (3 * PJBUF)      // 98304 (>= 67584 epilogue)

__global__ __launch_bounds__(256, 2) void proj_mma() {
    extern __shared__ char smem[];
    const uint32_t sb = smem_u32(smem);
    const int tid = threadIdx.x;
    const int w = tid >> 5, lane = tid & 31;
    const int b  = blockIdx.z;
    const int l0 = blockIdx.x * 128;
    const int o0 = blockIdx.y * 128;

    const int srow = tid >> 3, sch = tid & 7;
    const uint32_t sda = (uint32_t)(srow * 128 + sch * 16);
    const __half* pw  = g_whi + (size_t)(o0 + srow) * DD + sch * 8;
    const __half* pxh = g_xhi + ((size_t)b * DD + srow) * LL + l0 + sch * 8;

#define PREFETCH_PJ(stb) do { \
    cpa16((stb) + PJ_A + sda,          pw); \
    cpa16((stb) + PJ_A + sda + 4096,   pw + 32 * DD); \
    cpa16((stb) + PJ_A + sda + 8192,   pw + 64 * DD); \
    cpa16((stb) + PJ_A + sda + 12288,  pw + 96 * DD); \
    cpa16((stb) + PJ_B0 + sda,         pxh); \
    cpa16((stb) + PJ_B0 + sda + 4096,  pxh + (size_t)32 * LL); \
    cpa16((stb) + PJ_B1 + sda,         pxh + 64); \
    cpa16((stb) + PJ_B1 + sda + 4096,  pxh + (size_t)32 * LL + 64); \
    pw += 64; pxh += (size_t)64 * LL; \
} while (0)

    PREFETCH_PJ(sb);            CPA_COMMIT();
    PREFETCH_PJ(sb + PJBUF);    CPA_COMMIT();

    const int mi     = lane >> 3;
    const int arow   = w * 16 + ((mi & 1) << 3) + (lane & 7);
    const int acolh  = (mi >> 1) * 16;
    const int b_ksub = ((mi & 1) << 3) + (lane & 7);
    const int b_noct = mi >> 1;

    float c[16][4];
    #pragma unroll
    for (int i = 0; i < 16; i++)
        #pragma unroll
        for (int j = 0; j < 4; j++) c[i][j] = 0.f;

    uint32_t bufc = sb;
    uint32_t bufn = sb + 2 * PJBUF;
    for (int kc = 0; kc < 8; kc++) {
        if (kc == 7) { CPA_WAIT(0); } else { CPA_WAIT(1); }
        __syncthreads();
        if (kc + 2 < 8) {
            PREFETCH_PJ(bufn);
            CPA_COMMIT();
            bufn = (bufn == sb + 2 * PJBUF) ? sb : bufn + PJBUF;
        }

        #pragma unroll
        for (int ks = 0; ks < 4; ks++) {
            uint32_t ahi[4];
            uint32_t aoff = (uint32_t)(arow * 128 + ks * 32 + acolh);
            ldsm4(ahi, bufc + PJ_A + SWZ128(aoff));
            #pragma unroll
            for (int hb = 0; hb < 2; hb++) {
                const uint32_t bh = bufc + (hb ? PJ_B1 : PJ_B0);
                #pragma unroll
                for (int j = 0; j < 8; j += 2) {
                    uint32_t boff = (uint32_t)((ks * 16 + b_ksub) * 128 + (j + b_noct) * 16);
                    uint32_t bhi[4];
                    ldsm4t(bhi, bh + SWZ128(boff));
                    const int o1 = hb * 8 + j;
                    mma16816(c[o1],     ahi, bhi);
                    mma16816(c[o1 + 1], ahi, bhi + 2);
                }
            }
        }

        bufc = (bufc == sb + 2 * PJBUF) ? sb : bufc + PJBUF;
    }

    // ---- fragments -> smem [o][OSTRIDE] fp32 ----
    __syncthreads();
    float* Osm = (float*)smem;
    {
        const int r1 = w * 16 + (lane >> 2);
        const int cb = (lane & 3) << 1;
        #pragma unroll
        for (int oct = 0; oct < 16; oct++) {
            const int col = (oct >> 3) * 64 + (oct & 7) * 8 + cb;
            Osm[r1 * OSTRIDE + col]           = c[oct][0];
            Osm[r1 * OSTRIDE + col + 1]       = c[oct][1];
            Osm[(r1 + 8) * OSTRIDE + col]     = c[oct][2];
            Osm[(r1 + 8) * OSTRIDE + col + 1] = c[oct][3];
        }
    }
    __syncthreads();

    if (o0 >= 512 && o0 < 1024) {
        #pragma unroll
        for (int i = tid; i < 2048; i += 256) {
            int row = i >> 4, ch = i & 15;
            int vr = (o0 - 512) + row;
            const float* src = &Osm[row * OSTRIDE + ch * 8];
            __align__(16) __half hi8[8];
            #pragma unroll
            for (int k = 0; k < 8; k++)
                hi8[k] = __float2half_rn(src[k]);
            int seg = ch >> 3, pc = (ch & 7) ^ (vr & 7);
            size_t ge = ((size_t)b * DD + vr) * LL + l0 + seg * 64 + pc * 8;
            *(uint4*)&g_vhi[ge] = *(uint4*)hi8;
        }
    } else if (o0 < 512) {
        #pragma unroll
        for (int i = tid; i < 2048; i += 256) {
            int l = i >> 4, ch = i & 15;
            int gl = l0 + l;
            __align__(16) __half hi8[8];
            #pragma unroll
            for (int k = 0; k < 8; k++) {
                int rk = (k + lane) & 7;
                hi8[rk] = __float2half_rn(Osm[(ch * 8 + rk) * OSTRIDE + l]);
            }
            int seg = ch >> 3, pc = (ch & 7) ^ (gl & 7);
            size_t ge = ((size_t)b * LL + gl) * DD + o0 + seg * 64 + pc * 8;
            *(uint4*)&g_khi[ge] = *(uint4*)hi8;
        }
    } else {
        #pragma unroll
        for (int i = tid; i < 2048; i += 256) {
            int l = i >> 4, ch = i & 15;
            int gl = l0 + l;
            __align__(16) __half hi8[8];
            #pragma unroll
            for (int k = 0; k < 8; k++) {
                int rk = (k + lane) & 7;
                hi8[rk] = __float2half_rn(Osm[(ch * 8 + rk) * OSTRIDE + l] * 0.125f);
            }
            int seg = ch >> 3, pc = (ch & 7) ^ (gl & 7);
            size_t ge = ((size_t)b * LL + gl) * DD + (o0 - 1024) + seg * 64 + pc * 8;
            *(uint4*)&g_qhi[ge] = *(uint4*)hi8;
        }
    }
}

// ===========================================================================
// mma.sync flash attention (unchanged from Round 14, validated)
// ===========================================================================
#define ST_SIZE  16640            // KHI 8K | VHI 8K | MSKF 256
#define SM_TOTAL (3 * ST_SIZE)    // 49920

__global__ __launch_bounds__(256, 2) void attn_mma(float* __restrict__ out)
{
    extern __shared__ char smem[];
    const uint32_t sb = smem_u32(smem);
    const int tid  = threadIdx.x;
    const int w    = tid >> 5;
    const int lane = tid & 31;
    const int b = blockIdx.z, h = blockIdx.y, q0 = blockIdx.x * 128;

    const size_t qkrow0 = (size_t)b * LL * DD + (size_t)h * 64;
    const size_t vrow0  = ((size_t)b * DD + h * 64) * LL;

    const int srow = tid >> 3;
    const int sch  = tid & 7;
    const uint32_t sd = (uint32_t)(srow * 128 + sch * 16);

    const __half* pkh = g_khi + qkrow0 + (size_t)srow * DD + sch * 8;
    const __half* pvh = g_vhi + vrow0 + (size_t)srow * LL + sch * 8;
    const float*  pmk = g_mkf + (size_t)b * LL + tid * 4;

#define PREFETCH_TILE(stb) do { \
    cpa16((stb) + sd,                pkh); \
    cpa16((stb) + sd + 4096,         pkh + 32 * DD); \
    cpa16((stb) + 8192 + sd,         pvh); \
    cpa16((stb) + 8192 + sd + 4096,  pvh + (size_t)32 * LL); \
    if (tid < 16) cpa16((stb) + 16384 + tid * 16, pmk); \
    pkh += 64 * DD; pvh += 64; pmk += 64; \
} while (0)

    {
        const __half* pq = g_qhi + qkrow0 + (size_t)(q0 + srow) * DD + sch * 8;
        const uint32_t qst = sb + 2 * ST_SIZE;
        cpa16(qst + sd,          pq);
        cpa16(qst + sd + 4096,   pq + 32 * DD);
        cpa16(qst + sd + 8192,   pq + 64 * DD);
        cpa16(qst + sd + 12288,  pq + 96 * DD);
        CPA_COMMIT();
    }
    PREFETCH_TILE(sb);             CPA_COMMIT();
    PREFETCH_TILE(sb + ST_SIZE);   CPA_COMMIT();

    const int mi = lane >> 3;
    const int qrow_l = w * 16 + ((mi & 1) << 3) + (lane & 7);
    const int a_colh = (mi >> 1) * 16;
    const int b_rsub = ((mi >> 1) << 3) + (lane & 7);
    const int b_colh = (mi & 1) * 16;

    CPA_WAIT(2);
    __syncthreads();
    uint32_t qf[4][4];
    {
        const uint32_t qb2 = sb + 2 * ST_SIZE;
        #pragma unroll
        for (int kc = 0; kc < 4; kc++) {
            uint32_t qoff = (uint32_t)(qrow_l * 128 + kc * 32 + a_colh);
            ldsm4(qf[kc], qb2 + SWZ128(qoff));
        }
    }
    __syncthreads();

    float o_acc[8][4];
    #pragma unroll
    for (int i = 0; i < 8; i++)
        #pragma unroll
        for (int j = 0; j < 4; j++) o_acc[i][j] = 0.f;
    float lsum0 = 0.f, lsum1 = 0.f;

    uint32_t stc = sb;
    uint32_t stn = sb + 2 * ST_SIZE;

    for (int it = 0; it < 32; it++) {
        if (it == 31) { CPA_WAIT(0); } else { CPA_WAIT(1); }
        __syncthreads();

        if (it + 2 < 32) {
            PREFETCH_TILE(stn);
            CPA_COMMIT();
            stn = (stn == sb + 2 * ST_SIZE) ? sb : stn + ST_SIZE;
        }

        const uint32_t kh = stc, vh = stc + 8192;
        const float* mpf = (const float*)(smem + (stc - sb) + 16384);

        float s[8][4];
        #pragma unroll
        for (int i = 0; i < 8; i++)
            #pragma unroll
            for (int j = 0; j < 4; j++) s[i][j] = 0.f;

        #pragma unroll
        for (int kc = 0; kc < 4; kc++) {
            #pragma unroll
            for (int j = 0; j < 8; j += 2) {
                uint32_t bhi[4];
                uint32_t koff = (uint32_t)((j * 8 + b_rsub) * 128 + kc * 32 + b_colh);
                ldsm4(bhi, kh + SWZ128(koff));
                mma16816(s[j],     qf[kc], bhi);
                mma16816(s[j + 1], qf[kc], bhi + 2);
            }
        }

        uint32_t phiA[8], phiB[8];
        const int cb2 = (lane & 3) << 1;
        #pragma unroll
        for (int nt = 0; nt < 8; nt++) {
            float2 mf = *(const float2*)&mpf[nt * 8 + cb2];
            float p0 = __expf(s[nt][0]) * mf.x;
            float p1 = __expf(s[nt][1]) * mf.y;
            float p2 = __expf(s[nt][2]) * mf.x;
            float p3 = __expf(s[nt][3]) * mf.y;
            lsum0 += p0 + p1;
            lsum1 += p2 + p3;
            phiA[nt] = pack_h2(p0, p1);
            phiB[nt] = pack_h2(p2, p3);
        }

        #pragma unroll
        for (int kc = 0; kc < 4; kc++) {
            uint32_t ahi[4] = {phiA[2 * kc], phiB[2 * kc], phiA[2 * kc + 1], phiB[2 * kc + 1]};
            #pragma unroll
            for (int j = 0; j < 8; j += 2) {
                uint32_t bhi[4];
                uint32_t voff = (uint32_t)((j * 8 + b_rsub) * 128 + kc * 32 + b_colh);
                ldsm4(bhi, vh + SWZ128(voff));
                mma16816(o_acc[j],     ahi, bhi);
                mma16816(o_acc[j + 1], ahi, bhi + 2);
            }
        }

        stc = (stc == sb + 2 * ST_SIZE) ? sb : stc + ST_SIZE;
    }

    __syncthreads();

    #pragma unroll
    for (int off = 1; off < 4; off <<= 1) {
        lsum0 += __shfl_xor_sync(0xffffffffu, lsum0, off);
        lsum1 += __shfl_xor_sync(0xffffffffu, lsum1, off);
    }
    const float inv0 = 1.0f / lsum0, inv1 = 1.0f / lsum1;

    float* Osm = (float*)smem;
    const int r1 = w * 16 + (lane >> 2);
    const int cb = (lane & 3) << 1;
    #pragma unroll
    for (int nt = 0; nt < 8; nt++) {
        const int c0 = nt * 8 + cb;
        Osm[r1 * 66 + c0]           = o_acc[nt][0] * inv0;
        Osm[r1 * 66 + c0 + 1]       = o_acc[nt][1] * inv0;
        Osm[(r1 + 8) * 66 + c0]     = o_acc[nt][2] * inv1;
        Osm[(r1 + 8) * 66 + c0 + 1] = o_acc[nt][3] * inv1;
    }
    __syncthreads();
    {
        const int dh = tid >> 2;
        const int qc = (tid & 3) << 5;
        float* op = out + ((size_t)b * DD + h * 64 + dh) * LL + q0 + qc;
        #pragma unroll
        for (int i = 0; i < 8; i++) {
            float4 v = make_float4(Osm[(qc + 4 * i + 0) * 66 + dh],
                                   Osm[(qc + 4 * i + 1) * 66 + dh],
                                   Osm[(qc + 4 * i + 2) * 66 + dh],
                                   Osm[(qc + 4 * i + 3) * 66 + dh]);
            *(float4*)(op + 4 * i) = v;
        }
    }
}

// ===========================================================================
extern "C" void kernel_launch(void* const* d_in, const int* in_sizes, int n_in,
                              void* d_out, int out_size) {
    (void)in_sizes; (void)n_in; (void)out_size;
    const float* queries = (const float*)d_in[0];
    const int*   mask    = (const int*)d_in[1];
    const float* w_mem   = (const float*)d_in[2];
    const float* w_q     = (const float*)d_in[3];
    float* out = (float*)d_out;

    cvt_w<<<384, 256>>>(w_mem, w_q);
    cvt_q<<<4096, 256>>>(queries);
    cvt_m<<<64, 256>>>(mask);

    cudaFuncSetAttribute(proj_mma, cudaFuncAttributeMaxDynamicSharedMemorySize, P_TOTAL);
    dim3 gp(LL / 128, 1536 / 128, BB);
    proj_mma<<<gp, 256, P_TOTAL>>>();

    cudaFuncSetAttribute(attn_mma, cudaFuncAttributeMaxDynamicSharedMemorySize, SM_TOTAL);
    dim3 ga(LL / 128, HH, BB);
    attn_mma<<<ga, 256, SM_TOTAL>>>(out);
}